// round 8
// baseline (speedup 1.0000x reference)
#include <cuda_runtime.h>
#include <math.h>

#define NMAX 100000
#define EMAX 800000
#define INC  96
#define OUTC 64
#define SCAN_B 1024
#define NB_SCAN ((NMAX + SCAN_B - 1) / SCAN_B)
#define SXP (INC + 4)                  // padded sx row (100): kills LDS bank conflicts

// ---- scratch (static device globals; no allocation) ----
__device__ int    g_flag32;            // 1 => edge_index stored as int32
__device__ int    g_cnt[NMAX];
__device__ int    g_cursor[NMAX];
__device__ int    g_off[NMAX];
__device__ int    g_bsum[NB_SCAN + 1];
__device__ int    g_boff[NB_SCAN + 1];
__device__ float  g_dinv[NMAX];
__device__ int    g_row[EMAX];
__device__ int    g_col[EMAX];
__device__ int    g_srcidx[EMAX];
__device__ float  g_val[EMAX];
__device__ float4 g_bufA[NMAX * (OUTC / 4)];
__device__ float4 g_bufB[NMAX * (OUTC / 4)];

__device__ __forceinline__ unsigned long long fma2(unsigned long long a,
                                                   unsigned long long b,
                                                   unsigned long long c) {
    unsigned long long d;
    asm("fma.rn.f32x2 %0, %1, %2, %3;" : "=l"(d) : "l"(a), "l"(b), "l"(c));
    return d;
}

// init counters + dtype probe (odd 32-bit words all zero <=> int64 layout)
__global__ void k_init_detect(const int* __restrict__ p, int N) {
    int i = blockIdx.x * blockDim.x + threadIdx.x;
    if (i == 0) g_flag32 = 0;
    if (i < N) { g_cnt[i] = 0; g_cursor[i] = 0; }
    if (i < 1024) {
        if (p[2 * i + 1] != 0) atomicOr(&g_flag32, 1);
    }
}

// unified edge read (int32 or int64 words) + in-degree; bounds-guarded
__global__ void k_edge_pre(const int* __restrict__ p, int E, int N) {
    int e = blockIdx.x * blockDim.x + threadIdx.x;
    if (e < E) {
        int r, c;
        if (g_flag32) { r = p[e];     c = p[E + e]; }
        else          { r = p[2 * e]; c = p[2 * E + 2 * e]; }
        if ((unsigned)r >= (unsigned)N) r = 0;
        if ((unsigned)c >= (unsigned)N) c = 0;
        g_row[e] = r;
        g_col[e] = c;
        atomicAdd(&g_cnt[c], 1);
    }
}

// scan partial sums + fused dinv
__global__ void k_scan_partial(int N) {
    __shared__ int swarp[8];
    int b = blockIdx.x, t = threadIdx.x;
    int base = b * SCAN_B + t * 4;
    int s = 0;
#pragma unroll
    for (int k = 0; k < 4; k++) {
        int i = base + k;
        if (i < N) {
            int c = g_cnt[i];
            s += c;
            g_dinv[i] = rsqrtf((float)(c + 1));   // +1 self loop
        }
    }
#pragma unroll
    for (int d = 1; d < 32; d <<= 1) s += __shfl_xor_sync(0xffffffffu, s, d);
    if ((t & 31) == 0) swarp[t >> 5] = s;
    __syncthreads();
    if (t == 0) {
        int tot = 0;
#pragma unroll
        for (int w = 0; w < 8; w++) tot += swarp[w];
        g_bsum[b] = tot;
    }
}

__global__ void k_scan_bsum(int nb) {
    if (threadIdx.x == 0) {
        int acc = 0;
        for (int b = 0; b < nb; b++) { g_boff[b] = acc; acc += g_bsum[b]; }
    }
}

__global__ void k_scan_final(int N) {
    __shared__ int swsum[8];
    int b = blockIdx.x, t = threadIdx.x;
    int lane = t & 31, wid = t >> 5;
    int base = b * SCAN_B + t * 4;
    int v[4];
#pragma unroll
    for (int k = 0; k < 4; k++) {
        int i = base + k;
        v[k] = (i < N) ? g_cnt[i] : 0;
    }
    int s = v[0] + v[1] + v[2] + v[3];
    int incl = s;
#pragma unroll
    for (int d = 1; d < 32; d <<= 1) {
        int o = __shfl_up_sync(0xffffffffu, incl, d);
        if (lane >= d) incl += o;
    }
    if (lane == 31) swsum[wid] = incl;
    __syncthreads();
    int wexcl = 0;
#pragma unroll
    for (int w = 0; w < 8; w++) if (w < wid) wexcl += swsum[w];
    int texcl = wexcl + (incl - s) + g_boff[b];
#pragma unroll
    for (int k = 0; k < 4; k++) {
        int i = base + k;
        if (i < N) g_off[i] = texcl;
        texcl += v[k];
    }
}

__global__ void k_fill(int E) {
    int e = blockIdx.x * blockDim.x + threadIdx.x;
    if (e < E) {
        int r = g_row[e], c = g_col[e];
        int pos = g_off[c] + atomicAdd(&g_cursor[c], 1);
        if (pos < EMAX) {
            g_srcidx[pos] = r;
            g_val[pos] = g_dinv[r] * g_dinv[c];
        }
    }
}

// y = x @ W^T  -> g_bufA  using packed fma.rn.f32x2
// 256 threads: node = tid>>3 (32 nodes/tile), thread covers 8 outputs as 4 f32x2 pairs
__global__ void k_gemm(const float* __restrict__ x,
                       const float* __restrict__ W, int N) {
    __shared__ __align__(16) float sW[INC * OUTC];   // sW[k*64+o] = W[o][k]
    __shared__ __align__(16) float sx[32 * SXP];
    int tid = threadIdx.x;
    for (int t = tid; t < INC * OUTC; t += 256) {
        int o = t / INC, k = t % INC;
        sW[k * OUTC + o] = W[t];
    }
    __syncthreads();

    int node = tid >> 3;          // 0..31
    int og   = (tid & 7) * 8;     // 0,8,...,56
    int ntiles = (N + 31) >> 5;
    float* A = (float*)g_bufA;

    for (int tile = blockIdx.x; tile < ntiles; tile += gridDim.x) {
        int n0 = tile * 32;
        __syncthreads();
        if (n0 + 32 <= N) {       // fast path: vectorized tile load
            const float4* gx = (const float4*)(x + (size_t)n0 * INC);
            for (int t = tid; t < 32 * INC / 4; t += 256) {
                int el = t * 4;
                int nn = el / INC, k = el % INC;
                *(float4*)&sx[nn * SXP + k] = gx[t];
            }
        } else {
            for (int t = tid; t < 32 * INC; t += 256) {
                int nn = t / INC, k = t % INC;
                int gn = n0 + nn;
                sx[nn * SXP + k] = (gn < N) ? x[(size_t)gn * INC + k] : 0.0f;
            }
        }
        __syncthreads();
        int n = n0 + node;
        if (n < N) {
            unsigned long long acc0 = 0, acc1 = 0, acc2 = 0, acc3 = 0;
            const float* xr = &sx[node * SXP];
#pragma unroll
            for (int k = 0; k < INC; k++) {
                unsigned int xu = __float_as_uint(xr[k]);
                unsigned long long a;
                asm("mov.b64 %0, {%1, %1};" : "=l"(a) : "r"(xu));
                const ulonglong2* wp = (const ulonglong2*)&sW[k * OUTC + og];
                ulonglong2 p0 = wp[0];
                ulonglong2 p1 = wp[1];
                acc0 = fma2(a, p0.x, acc0);
                acc1 = fma2(a, p0.y, acc1);
                acc2 = fma2(a, p1.x, acc2);
                acc3 = fma2(a, p1.y, acc3);
            }
            ulonglong2* outp = (ulonglong2*)&A[(size_t)n * OUTC + og];
            outp[0] = make_ulonglong2(acc0, acc1);
            outp[1] = make_ulonglong2(acc2, acc3);
        }
    }
}

// One warp per destination node, ×4-unrolled gather for MLP.
// final!=0: apply bias + sigmoid and write to `out` instead of dst buffer.
__global__ void k_hop(int dir, int N, int final,
                      const float* __restrict__ bias, float* __restrict__ out) {
    const float2* __restrict__ src = (const float2*)(dir ? g_bufB : g_bufA);
    float2*                    dst = (float2*)(dir ? g_bufA : g_bufB);
    int gw   = (blockIdx.x * blockDim.x + threadIdx.x) >> 5;
    int lane = threadIdx.x & 31;
    if (gw >= N) return;
    int v   = gw;
    int beg = g_off[v];
    int cnt = g_cnt[v];
    float dv = g_dinv[v];
    float sl = dv * dv;
    float2 s = src[v * 32 + lane];
    float ax = s.x * sl;
    float ay = s.y * sl;

    int j = beg, end = beg + cnt;
    while (j < end) {
        int m = end - j;
        if (m > 32) m = 32;
        int idx = 0; float w = 0.0f;
        if (lane < m) { idx = g_srcidx[j + lane]; w = g_val[j + lane]; }
        int k = 0;
        for (; k + 4 <= m; k += 4) {
            int   r0 = __shfl_sync(0xffffffffu, idx, k);
            int   r1 = __shfl_sync(0xffffffffu, idx, k + 1);
            int   r2 = __shfl_sync(0xffffffffu, idx, k + 2);
            int   r3 = __shfl_sync(0xffffffffu, idx, k + 3);
            float w0 = __shfl_sync(0xffffffffu, w, k);
            float w1 = __shfl_sync(0xffffffffu, w, k + 1);
            float w2 = __shfl_sync(0xffffffffu, w, k + 2);
            float w3 = __shfl_sync(0xffffffffu, w, k + 3);
            float2 v0 = src[r0 * 32 + lane];
            float2 v1 = src[r1 * 32 + lane];
            float2 v2 = src[r2 * 32 + lane];
            float2 v3 = src[r3 * 32 + lane];
            ax += w0 * v0.x; ay += w0 * v0.y;
            ax += w1 * v1.x; ay += w1 * v1.y;
            ax += w2 * v2.x; ay += w2 * v2.y;
            ax += w3 * v3.x; ay += w3 * v3.y;
        }
        for (; k < m; k++) {
            int   r  = __shfl_sync(0xffffffffu, idx, k);
            float wk = __shfl_sync(0xffffffffu, w, k);
            float2 xv = src[r * 32 + lane];
            ax += wk * xv.x;
            ay += wk * xv.y;
        }
        j += 32;
    }

    if (final) {
        float2 bb = *(const float2*)&bias[2 * lane];
        float2 o;
        o.x = 1.0f / (1.0f + __expf(-(ax + bb.x)));
        o.y = 1.0f / (1.0f + __expf(-(ay + bb.y)));
        *(float2*)&out[(size_t)v * OUTC + 2 * lane] = o;
    } else {
        float2 o; o.x = ax; o.y = ay;
        dst[v * 32 + lane] = o;
    }
}

extern "C" void kernel_launch(void* const* d_in, const int* in_sizes, int n_in,
                              void* d_out, int out_size) {
    const float* x  = (const float*)d_in[0];
    const int*   ei = (const int*)d_in[1];
    const float* W  = (const float*)d_in[2];
    const float* b  = (const float*)d_in[3];
    float*       out = (float*)d_out;

    int N = in_sizes[0] / INC;
    int E = 800000;
    int nb = (N + SCAN_B - 1) / SCAN_B;

    k_init_detect<<<(N + 255) / 256, 256>>>(ei, N);
    k_edge_pre<<<(E + 255) / 256, 256>>>(ei, E, N);

    k_scan_partial<<<nb, 256>>>(N);       // + fused dinv
    k_scan_bsum<<<1, 32>>>(nb);
    k_scan_final<<<nb, 256>>>(N);
    k_fill<<<(E + 255) / 256, 256>>>(E);

    k_gemm<<<2048, 256>>>(x, W, N);       // x @ W^T -> A  (f32x2 packed FFMA)

    int hop_blocks = (N * 32 + 255) / 256;
    k_hop<<<hop_blocks, 256>>>(0, N, 0, b, out);   // A -> B
    k_hop<<<hop_blocks, 256>>>(1, N, 1, b, out);   // B -> sigmoid -> out
}

// round 9
// speedup vs baseline: 1.1197x; 1.1197x over previous
#include <cuda_runtime.h>
#include <math.h>

#define NMAX 100000
#define EMAX 800000
#define INC  96
#define OUTC 64
#define SCAN_B 1024
#define NB_SCAN ((NMAX + SCAN_B - 1) / SCAN_B)
#define SXP (INC + 4)

// ---- scratch (static device globals; no allocation) ----
__device__ int    g_flag32;
__device__ int    g_cnt[NMAX];
__device__ int    g_cursor[NMAX];
__device__ int    g_off[NMAX];
__device__ int    g_bsum[NB_SCAN + 1];
__device__ int    g_boff[NB_SCAN + 1];
__device__ float  g_dinv[NMAX];
__device__ int    g_row[EMAX];
__device__ int    g_col[EMAX];
__device__ int2   g_csr[EMAX];         // packed CSR: {srcidx, norm bits}
__device__ float4 g_bufA[NMAX * (OUTC / 4)];
__device__ float4 g_bufB[NMAX * (OUTC / 4)];

__device__ __forceinline__ unsigned long long fma2(unsigned long long a,
                                                   unsigned long long b,
                                                   unsigned long long c) {
    unsigned long long d;
    asm("fma.rn.f32x2 %0, %1, %2, %3;" : "=l"(d) : "l"(a), "l"(b), "l"(c));
    return d;
}

__global__ void k_init_detect(const int* __restrict__ p, int N) {
    int i = blockIdx.x * blockDim.x + threadIdx.x;
    if (i == 0) g_flag32 = 0;
    if (i < N) { g_cnt[i] = 0; g_cursor[i] = 0; }
    if (i < 1024) {
        if (p[2 * i + 1] != 0) atomicOr(&g_flag32, 1);
    }
}

// unified edge read (int32 or int64 words) + in-degree; bounds-guarded
__global__ void k_edge_pre(const int* __restrict__ p, int E, int N) {
    int e = blockIdx.x * blockDim.x + threadIdx.x;
    if (e < E) {
        int r, c;
        if (g_flag32) {
            r = p[e]; c = p[E + e];
        } else {
            const int2* p2 = (const int2*)p;      // int64 low/high words
            r = p2[e].x; c = p2[E + e].x;
        }
        if ((unsigned)r >= (unsigned)N) r = 0;
        if ((unsigned)c >= (unsigned)N) c = 0;
        g_row[e] = r;
        g_col[e] = c;
        atomicAdd(&g_cnt[c], 1);
    }
}

// scan partial sums + fused dinv
__global__ void k_scan_partial(int N) {
    __shared__ int swarp[8];
    int b = blockIdx.x, t = threadIdx.x;
    int base = b * SCAN_B + t * 4;
    int s = 0;
#pragma unroll
    for (int k = 0; k < 4; k++) {
        int i = base + k;
        if (i < N) {
            int c = g_cnt[i];
            s += c;
            g_dinv[i] = rsqrtf((float)(c + 1));
        }
    }
#pragma unroll
    for (int d = 1; d < 32; d <<= 1) s += __shfl_xor_sync(0xffffffffu, s, d);
    if ((t & 31) == 0) swarp[t >> 5] = s;
    __syncthreads();
    if (t == 0) {
        int tot = 0;
#pragma unroll
        for (int w = 0; w < 8; w++) tot += swarp[w];
        g_bsum[b] = tot;
    }
}

// parallel warp scan of block sums (was 8.2us serial; now ~1us)
__global__ void k_scan_bsum(int nb) {
    int lane = threadIdx.x;
    int carry = 0;
    for (int base = 0; base < nb; base += 32) {
        int i = base + lane;
        int v = (i < nb) ? g_bsum[i] : 0;
        int incl = v;
#pragma unroll
        for (int d = 1; d < 32; d <<= 1) {
            int o = __shfl_up_sync(0xffffffffu, incl, d);
            if (lane >= d) incl += o;
        }
        if (i < nb) g_boff[i] = carry + incl - v;
        carry += __shfl_sync(0xffffffffu, incl, 31);
    }
}

__global__ void k_scan_final(int N) {
    __shared__ int swsum[8];
    int b = blockIdx.x, t = threadIdx.x;
    int lane = t & 31, wid = t >> 5;
    int base = b * SCAN_B + t * 4;
    int v[4];
#pragma unroll
    for (int k = 0; k < 4; k++) {
        int i = base + k;
        v[k] = (i < N) ? g_cnt[i] : 0;
    }
    int s = v[0] + v[1] + v[2] + v[3];
    int incl = s;
#pragma unroll
    for (int d = 1; d < 32; d <<= 1) {
        int o = __shfl_up_sync(0xffffffffu, incl, d);
        if (lane >= d) incl += o;
    }
    if (lane == 31) swsum[wid] = incl;
    __syncthreads();
    int wexcl = 0;
#pragma unroll
    for (int w = 0; w < 8; w++) if (w < wid) wexcl += swsum[w];
    int texcl = wexcl + (incl - s) + g_boff[b];
#pragma unroll
    for (int k = 0; k < 4; k++) {
        int i = base + k;
        if (i < N) g_off[i] = texcl;
        texcl += v[k];
    }
}

__global__ void k_fill(int E) {
    int e = blockIdx.x * blockDim.x + threadIdx.x;
    if (e < E) {
        int r = g_row[e], c = g_col[e];
        int pos = g_off[c] + atomicAdd(&g_cursor[c], 1);
        if (pos < EMAX) {
            float nm = g_dinv[r] * g_dinv[c];
            g_csr[pos] = make_int2(r, __float_as_int(nm));
        }
    }
}

// y = x @ W^T -> g_bufA  (packed fma.rn.f32x2; 8 outputs/thread)
__global__ void k_gemm(const float* __restrict__ x,
                       const float* __restrict__ W, int N) {
    __shared__ __align__(16) float sW[INC * OUTC];
    __shared__ __align__(16) float sx[32 * SXP];
    int tid = threadIdx.x;
    for (int t = tid; t < INC * OUTC; t += 256) {
        int o = t / INC, k = t % INC;
        sW[k * OUTC + o] = W[t];
    }
    __syncthreads();

    int node = tid >> 3;
    int og   = (tid & 7) * 8;
    int ntiles = (N + 31) >> 5;
    float* A = (float*)g_bufA;

    for (int tile = blockIdx.x; tile < ntiles; tile += gridDim.x) {
        int n0 = tile * 32;
        __syncthreads();
        if (n0 + 32 <= N) {
            const float4* gx = (const float4*)(x + (size_t)n0 * INC);
            for (int t = tid; t < 32 * INC / 4; t += 256) {
                int el = t * 4;
                int nn = el / INC, k = el % INC;
                *(float4*)&sx[nn * SXP + k] = gx[t];
            }
        } else {
            for (int t = tid; t < 32 * INC; t += 256) {
                int nn = t / INC, k = t % INC;
                int gn = n0 + nn;
                sx[nn * SXP + k] = (gn < N) ? x[(size_t)gn * INC + k] : 0.0f;
            }
        }
        __syncthreads();
        int n = n0 + node;
        if (n < N) {
            unsigned long long acc0 = 0, acc1 = 0, acc2 = 0, acc3 = 0;
            const float* xr = &sx[node * SXP];
#pragma unroll
            for (int k = 0; k < INC; k++) {
                unsigned int xu = __float_as_uint(xr[k]);
                unsigned long long a;
                asm("mov.b64 %0, {%1, %1};" : "=l"(a) : "r"(xu));
                const ulonglong2* wp = (const ulonglong2*)&sW[k * OUTC + og];
                ulonglong2 p0 = wp[0];
                ulonglong2 p1 = wp[1];
                acc0 = fma2(a, p0.x, acc0);
                acc1 = fma2(a, p0.y, acc1);
                acc2 = fma2(a, p1.x, acc2);
                acc3 = fma2(a, p1.y, acc3);
            }
            ulonglong2* outp = (ulonglong2*)&A[(size_t)n * OUTC + og];
            outp[0] = make_ulonglong2(acc0, acc1);
            outp[1] = make_ulonglong2(acc2, acc3);
        }
    }
}

// Hop: 2 nodes per warp (half-warp each), float4 lanes, packed CSR.
// Per shfl step serves one edge per half-warp => ~2x less warp-serial work.
__global__ void k_hop(int dir, int N, int final,
                      const float* __restrict__ bias, float* __restrict__ out) {
    const float4* __restrict__ src = dir ? g_bufB : g_bufA;
    float4*                    dst = dir ? g_bufA : g_bufB;
    int gw   = (blockIdx.x * blockDim.x + threadIdx.x) >> 5;
    int lane = threadIdx.x & 31;
    int half = lane >> 4;
    int hl   = lane & 15;

    int v = gw * 2 + half;
    bool valid = (v < N);
    int vc = valid ? v : 0;

    int beg = g_off[vc];
    int cnt = valid ? g_cnt[vc] : 0;
    float dv = g_dinv[vc];
    float sl = dv * dv;
    float4 s = src[vc * 16 + hl];
    float4 acc;
    acc.x = s.x * sl; acc.y = s.y * sl; acc.z = s.z * sl; acc.w = s.w * sl;

    int nch = (cnt + 15) >> 4;
    int nchmax = __reduce_max_sync(0xffffffffu, nch);

    for (int c = 0; c < nchmax; c++) {
        int m = cnt - c * 16;
        if (m > 16) m = 16;
        if (m < 0)  m = 0;
        int idx = 0; float w = 0.0f;
        if (hl < m) {
            int2 ev = g_csr[beg + c * 16 + hl];
            idx = ev.x;
            w   = __int_as_float(ev.y);
        }
        int mmax = __reduce_max_sync(0xffffffffu, m);
        int k = 0;
        for (; k + 2 <= mmax; k += 2) {
            int   r0 = __shfl_sync(0xffffffffu, idx, k,     16);
            int   r1 = __shfl_sync(0xffffffffu, idx, k + 1, 16);
            float w0 = __shfl_sync(0xffffffffu, w,   k,     16);
            float w1 = __shfl_sync(0xffffffffu, w,   k + 1, 16);
            float4 x0 = src[r0 * 16 + hl];
            float4 x1 = src[r1 * 16 + hl];
            acc.x += w0 * x0.x; acc.y += w0 * x0.y;
            acc.z += w0 * x0.z; acc.w += w0 * x0.w;
            acc.x += w1 * x1.x; acc.y += w1 * x1.y;
            acc.z += w1 * x1.z; acc.w += w1 * x1.w;
        }
        if (k < mmax) {
            int   r0 = __shfl_sync(0xffffffffu, idx, k, 16);
            float w0 = __shfl_sync(0xffffffffu, w,   k, 16);
            float4 x0 = src[r0 * 16 + hl];
            acc.x += w0 * x0.x; acc.y += w0 * x0.y;
            acc.z += w0 * x0.z; acc.w += w0 * x0.w;
        }
    }

    if (valid) {
        if (final) {
            float4 bb = *(const float4*)&bias[hl * 4];
            float4 o;
            o.x = 1.0f / (1.0f + __expf(-(acc.x + bb.x)));
            o.y = 1.0f / (1.0f + __expf(-(acc.y + bb.y)));
            o.z = 1.0f / (1.0f + __expf(-(acc.z + bb.z)));
            o.w = 1.0f / (1.0f + __expf(-(acc.w + bb.w)));
            ((float4*)out)[(size_t)v * 16 + hl] = o;
        } else {
            dst[v * 16 + hl] = acc;
        }
    }
}

extern "C" void kernel_launch(void* const* d_in, const int* in_sizes, int n_in,
                              void* d_out, int out_size) {
    const float* x  = (const float*)d_in[0];
    const int*   ei = (const int*)d_in[1];
    const float* W  = (const float*)d_in[2];
    const float* b  = (const float*)d_in[3];
    float*       out = (float*)d_out;

    int N = in_sizes[0] / INC;
    int E = 800000;
    int nb = (N + SCAN_B - 1) / SCAN_B;

    k_init_detect<<<(N + 255) / 256, 256>>>(ei, N);
    k_edge_pre<<<(E + 255) / 256, 256>>>(ei, E, N);

    k_scan_partial<<<nb, 256>>>(N);
    k_scan_bsum<<<1, 32>>>(nb);
    k_scan_final<<<nb, 256>>>(N);
    k_fill<<<(E + 255) / 256, 256>>>(E);

    k_gemm<<<2048, 256>>>(x, W, N);

    int nwarp = (N + 1) / 2;
    int hop_blocks = (nwarp * 32 + 255) / 256;
    k_hop<<<hop_blocks, 256>>>(0, N, 0, b, out);   // A -> B
    k_hop<<<hop_blocks, 256>>>(1, N, 1, b, out);   // B -> sigmoid -> out
}